// round 4
// baseline (speedup 1.0000x reference)
#include <cuda_runtime.h>
#include <cuda_bf16.h>
#include <cstdint>

#define NPROMPT 20
#define PROWS 4   // rows (b,l positions) per block in the fused kernel

// ---------------------------------------------------------------------------
// Fallback-path scratch (only used when shapes don't fit the fused kernel).
// ---------------------------------------------------------------------------
__device__ int g_rank[1 << 16];
__device__ int g_sid64;

// ===========================================================================
// FUSED KERNEL: rank scan + sid dtype probe + mask output + splice copy.
// Requires: L % PROWS == 0, D % 4 == 0, mask 16B-aligned (harness allocs are).
// One block handles PROWS consecutive rows of the same batch row.
// ===========================================================================
__global__ void __launch_bounds__(256) fused_splice_kernel(
    const int* __restrict__ mask,
    const float4* __restrict__ in,
    const float4* __restrict__ prompts,
    const void* __restrict__ sid_raw,
    float4* __restrict__ out,
    float* __restrict__ mask_out,
    int B, int L, int Dv, long long NS)
{
    int row0 = blockIdx.x * PROWS;
    int b = row0 / L;
    int l0 = row0 % L;

    // ---- pad-prefix count before l0 (cooperative, int4 loads, L2-resident) ----
    int cnt = 0;
    const int4* mrow4 = (const int4*)(mask + (size_t)b * L);
    int nq = l0 >> 2;                       // l0 is a multiple of PROWS (>=4)
    for (int q = threadIdx.x; q < nq; q += blockDim.x) {
        int4 v = mrow4[q];
        cnt += (v.x == 0) + (v.y == 0) + (v.z == 0) + (v.w == 0);
    }
    #pragma unroll
    for (int o = 16; o > 0; o >>= 1)
        cnt += __shfl_down_sync(0xFFFFFFFFu, cnt, o);

    __shared__ int wsum[8];
    int lane = threadIdx.x & 31, w = threadIdx.x >> 5;
    int nwarps = (blockDim.x + 31) >> 5;
    if (lane == 0) wsum[w] = cnt;
    __syncthreads();
    int prefix = 0;
    for (int i = 0; i < nwarps; ++i) prefix += wsum[i];

    // ---- per-position mask value, rank, take flag ----
    int mv[PROWS], r[PROWS];
    const int* mrow = mask + (size_t)b * L;
    int run = prefix;
    #pragma unroll
    for (int j = 0; j < PROWS; ++j) {
        mv[j] = mrow[l0 + j];               // broadcast L1 hits
        int pad = (mv[j] == 0);
        r[j] = (pad && run < NPROMPT) ? run : -1;
        run += pad;
    }

    if (mask_out && threadIdx.x < PROWS) {
        int j = threadIdx.x;
        mask_out[(size_t)row0 + j] = (r[j] >= 0) ? 1.0f : (float)mv[j];
    }

    bool need_sid = (r[0] >= 0) | (r[1] >= 0) | (r[2] >= 0) | (r[3] >= 0);

    if (!need_sid) {
        // ---- FAST PATH: contiguous copy of PROWS*Dv float4s ----
        size_t base = (size_t)row0 * Dv;
        int n = PROWS * Dv;
        #pragma unroll 4
        for (int c = threadIdx.x; c < n; c += blockDim.x) {
            out[base + c] = in[base + c];
        }
        return;
    }

    // ---- SLOW PATH (rare): resolve sid (dtype-probed), per-row source ----
    // Probe: buffer is int64 iff all odd 32-bit words among the first B words
    // are zero (ids < 2^31; B random ids make false positive ~impossible).
    // Reading B words is in-bounds for both int32[B] and int64[B].
    const int* sw = (const int*)sid_raw;
    int all0 = 1;
    for (int i = 1; i < B; i += 2)
        if (sw[i] != 0) { all0 = 0; break; }
    long long s = all0 ? ((const long long*)sid_raw)[b] : (long long)sw[b];
    if (s < 0) s = 0;
    if (s >= NS) s = NS - 1;

    #pragma unroll
    for (int j = 0; j < PROWS; ++j) {
        size_t base = ((size_t)row0 + j) * Dv;
        if (r[j] < 0) {
            for (int c = threadIdx.x; c < Dv; c += blockDim.x)
                out[base + c] = in[base + c];
        } else {
            size_t pb = ((size_t)s * NPROMPT + r[j]) * (size_t)Dv;
            for (int c = threadIdx.x; c < Dv; c += blockDim.x)
                out[base + c] = prompts[pb + c];
        }
    }
}

// ===========================================================================
// FALLBACK PATH (proven 3-kernel pipeline) for unexpected shapes.
// ===========================================================================
__global__ void probe_sid_kernel(const int* __restrict__ sid_words, int B) {
    if (threadIdx.x == 0 && blockIdx.x == 0) {
        int all_hi_zero = 1;
        for (int i = 1; i < B; i += 2)
            if (sid_words[i] != 0) { all_hi_zero = 0; break; }
        g_sid64 = all_hi_zero;
    }
}

__global__ void rank_mask_serial_kernel(const int* __restrict__ mask, int B, int L,
                                        float* __restrict__ mask_out) {
    int b = blockIdx.x * blockDim.x + threadIdx.x;
    if (b >= B) return;
    int cnt = 0;
    for (int l = 0; l < L; ++l) {
        int m = mask[(size_t)b * L + l];
        int is_pad = (m == 0);
        int take = is_pad && (cnt < NPROMPT);
        g_rank[(size_t)b * L + l] = take ? cnt : -1;
        if (mask_out) mask_out[(size_t)b * L + l] = take ? 1.0f : (float)m;
        cnt += is_pad;
    }
}

__global__ void splice_copy_scalar_kernel(const float* __restrict__ in,
                                          const float* __restrict__ prompts,
                                          const void* __restrict__ sid_raw,
                                          float* __restrict__ out,
                                          int L, int D, long long NS) {
    int row = blockIdx.x;
    int r = g_rank[row];
    size_t base = (size_t)row * D;
    if (r < 0) {
        for (int c = threadIdx.x; c < D; c += blockDim.x)
            out[base + c] = in[base + c];
    } else {
        int b = row / L;
        long long s = g_sid64 ? ((const long long*)sid_raw)[b]
                              : (long long)((const int*)sid_raw)[b];
        if (s < 0) s = 0;
        if (s >= NS) s = NS - 1;
        size_t pbase = ((size_t)s * NPROMPT + r) * (size_t)D;
        for (int c = threadIdx.x; c < D; c += blockDim.x)
            out[base + c] = prompts[pbase + c];
    }
}

// ===========================================================================
extern "C" void kernel_launch(void* const* d_in, const int* in_sizes, int n_in,
                              void* d_out, int out_size) {
    // Bind inputs by size rank (robust to ordering):
    //   smallest     -> sample_id_tensor [B]
    //   2nd smallest -> attention_mask   [B*L]
    //   2nd largest  -> input_embeds     [B*L*D]
    //   largest      -> prompt_embeddings [NS*NPROMPT*D]
    int idx[4] = {0, 1, 2, 3};
    for (int i = 0; i < 4; ++i)
        for (int j = i + 1; j < 4; ++j)
            if (in_sizes[idx[j]] < in_sizes[idx[i]]) {
                int t = idx[i]; idx[i] = idx[j]; idx[j] = t;
            }
    const void*  sid     = d_in[idx[0]];
    const int*   mask    = (const int*)d_in[idx[1]];
    const float* embeds  = (const float*)d_in[idx[2]];
    const float* prompts = (const float*)d_in[idx[3]];

    int B  = in_sizes[idx[0]];
    int BL = in_sizes[idx[1]];
    int L  = BL / B;
    long long D  = (long long)in_sizes[idx[2]] / BL;
    long long NS = (long long)in_sizes[idx[3]] / (NPROMPT * D);

    float* out = (float*)d_out;
    size_t embed_elems = (size_t)BL * (size_t)D;
    float* mask_out = ((size_t)out_size >= embed_elems + (size_t)BL)
                          ? out + embed_elems
                          : nullptr;

    if ((D & 3) == 0 && (L % PROWS) == 0) {
        int Dv = (int)(D >> 2);
        int blocks = BL / PROWS;
        fused_splice_kernel<<<blocks, 256>>>(
            mask, (const float4*)embeds, (const float4*)prompts, sid,
            (float4*)out, mask_out, B, L, Dv, NS);
    } else {
        probe_sid_kernel<<<1, 32>>>((const int*)sid, B);
        int threads = 128;
        int blocks = (B + threads - 1) / threads;
        rank_mask_serial_kernel<<<blocks, threads>>>(mask, B, (int)L, mask_out);
        int cthreads = (int)(D < 1024 ? ((D + 31) / 32) * 32 : 1024);
        splice_copy_scalar_kernel<<<BL, cthreads>>>(
            embeds, prompts, sid, out, (int)L, (int)D, NS);
    }
}

// round 5
// speedup vs baseline: 1.2131x; 1.2131x over previous
#include <cuda_runtime.h>
#include <cuda_bf16.h>
#include <cstdint>

#define NPROMPT 20

// Per-row resolved source base address (points into input_embeds or prompts).
__device__ unsigned long long g_src[1 << 16];
__device__ int g_sid64;   // fallback path only

// ===========================================================================
// Kernel A: probe sid dtype + pad-rank ballot scan + mask output + resolve
// per-row source addresses. One block per batch row (L <= 1024).
// ===========================================================================
__global__ void prep_kernel(const int* __restrict__ mask,
                            const float* __restrict__ in,
                            const float* __restrict__ prompts,
                            const void* __restrict__ sid_raw,
                            float* __restrict__ mask_out,
                            int B, int L, int D, long long NS) {
    int b = blockIdx.x;
    int t = threadIdx.x;

    // sid dtype probe (cheap, L1/L2 hits): int64 iff all odd 32-bit words
    // among the first B words are zero (ids < 2^31).
    const int* sw = (const int*)sid_raw;
    int all0 = 1;
    for (int i = 1; i < B; i += 2)
        if (sw[i] != 0) { all0 = 0; break; }
    long long s = all0 ? ((const long long*)sid_raw)[b] : (long long)sw[b];
    if (s < 0) s = 0;
    if (s >= NS) s = NS - 1;

    int m = 0, pad = 0;
    if (t < L) {
        m = mask[(size_t)b * L + t];
        pad = (m == 0);
    }
    unsigned bal = __ballot_sync(0xFFFFFFFFu, pad);
    int lane = t & 31;
    int warp = t >> 5;

    __shared__ int wtot[32];
    if (lane == 0) wtot[warp] = __popc(bal);
    __syncthreads();

    int prefix = 0;
    for (int w = 0; w < warp; ++w) prefix += wtot[w];
    int rank = prefix + __popc(bal & ((1u << lane) - 1u));

    if (t < L) {
        int take = (pad && rank < NPROMPT);
        size_t row = (size_t)b * L + t;
        const float* src = take
            ? prompts + ((size_t)s * NPROMPT + rank) * (size_t)D
            : in + row * (size_t)D;
        g_src[row] = (unsigned long long)src;
        if (mask_out) mask_out[row] = take ? 1.0f : (float)m;
    }
}

// ===========================================================================
// Kernel B: pure streaming copy. One warp per row; DV float4s per row,
// fully unrolled (DV/32 iterations): front-batched LDG.128s -> MLP = DV/32.
// ===========================================================================
template <int DV>
__global__ void __launch_bounds__(256) copy_rows_kernel(
    float4* __restrict__ out, int BL) {
    int gw = (blockIdx.x * blockDim.x + threadIdx.x) >> 5;
    if (gw >= BL) return;
    int lane = threadIdx.x & 31;

    const float4* __restrict__ src = (const float4*)g_src[gw];
    float4* __restrict__ dst = out + (size_t)gw * DV;

    float4 v[DV / 32];
    #pragma unroll
    for (int i = 0; i < DV / 32; ++i) v[i] = src[lane + i * 32];
    #pragma unroll
    for (int i = 0; i < DV / 32; ++i) dst[lane + i * 32] = v[i];
}

// Generic copy (runtime Dv) fallback.
__global__ void copy_rows_generic_kernel(float4* __restrict__ out,
                                         int BL, int Dv) {
    int gw = (blockIdx.x * blockDim.x + threadIdx.x) >> 5;
    if (gw >= BL) return;
    int lane = threadIdx.x & 31;
    const float4* __restrict__ src = (const float4*)g_src[gw];
    float4* __restrict__ dst = out + (size_t)gw * Dv;
    for (int c = lane; c < Dv; c += 32) dst[c] = src[c];
}

// ===========================================================================
// Fallback path for unexpected shapes (L > 1024 or D % 4 != 0).
// ===========================================================================
__global__ void prep_serial_kernel(const int* __restrict__ mask,
                                   const float* __restrict__ in,
                                   const float* __restrict__ prompts,
                                   const void* __restrict__ sid_raw,
                                   float* __restrict__ mask_out,
                                   int B, int L, int D, long long NS) {
    int b = blockIdx.x * blockDim.x + threadIdx.x;
    if (b >= B) return;
    const int* sw = (const int*)sid_raw;
    int all0 = 1;
    for (int i = 1; i < B; i += 2)
        if (sw[i] != 0) { all0 = 0; break; }
    long long s = all0 ? ((const long long*)sid_raw)[b] : (long long)sw[b];
    if (s < 0) s = 0;
    if (s >= NS) s = NS - 1;
    int cnt = 0;
    for (int l = 0; l < L; ++l) {
        size_t row = (size_t)b * L + l;
        int m = mask[row];
        int pad = (m == 0);
        int take = pad && (cnt < NPROMPT);
        const float* src = take
            ? prompts + ((size_t)s * NPROMPT + cnt) * (size_t)D
            : in + row * (size_t)D;
        g_src[row] = (unsigned long long)src;
        if (mask_out) mask_out[row] = take ? 1.0f : (float)m;
        cnt += pad;
    }
}

__global__ void copy_scalar_kernel(float* __restrict__ out, int BL, int D) {
    int row = blockIdx.x;
    if (row >= BL) return;
    const float* __restrict__ src = (const float*)g_src[row];
    float* __restrict__ dst = out + (size_t)row * D;
    for (int c = threadIdx.x; c < D; c += blockDim.x) dst[c] = src[c];
}

// ===========================================================================
extern "C" void kernel_launch(void* const* d_in, const int* in_sizes, int n_in,
                              void* d_out, int out_size) {
    // Bind inputs by size rank:
    //   smallest     -> sample_id_tensor [B]
    //   2nd smallest -> attention_mask   [B*L]
    //   2nd largest  -> input_embeds     [B*L*D]
    //   largest      -> prompt_embeddings [NS*NPROMPT*D]
    int idx[4] = {0, 1, 2, 3};
    for (int i = 0; i < 4; ++i)
        for (int j = i + 1; j < 4; ++j)
            if (in_sizes[idx[j]] < in_sizes[idx[i]]) {
                int t = idx[i]; idx[i] = idx[j]; idx[j] = t;
            }
    const void*  sid     = d_in[idx[0]];
    const int*   mask    = (const int*)d_in[idx[1]];
    const float* embeds  = (const float*)d_in[idx[2]];
    const float* prompts = (const float*)d_in[idx[3]];

    int B  = in_sizes[idx[0]];
    int BL = in_sizes[idx[1]];
    int L  = BL / B;
    long long D  = (long long)in_sizes[idx[2]] / BL;
    long long NS = (long long)in_sizes[idx[3]] / (NPROMPT * D);

    float* out = (float*)d_out;
    size_t embed_elems = (size_t)BL * (size_t)D;
    float* mask_out = ((size_t)out_size >= embed_elems + (size_t)BL)
                          ? out + embed_elems
                          : nullptr;

    // --- Kernel A: resolve per-row source addresses + mask output ---
    if (L <= 1024) {
        int threads = ((L + 31) / 32) * 32;
        prep_kernel<<<B, threads>>>(mask, embeds, prompts, sid,
                                    mask_out, B, L, (int)D, NS);
    } else {
        int threads = 128;
        int blocks = (B + threads - 1) / threads;
        prep_serial_kernel<<<blocks, threads>>>(mask, embeds, prompts, sid,
                                                mask_out, B, L, (int)D, NS);
    }

    // --- Kernel B: streaming copy ---
    if ((D & 3) == 0) {
        int Dv = (int)(D >> 2);
        int warps = BL;
        int threads = 256;
        int blocks = (warps * 32 + threads - 1) / threads;
        if (Dv == 192) {
            copy_rows_kernel<192><<<blocks, threads>>>((float4*)out, BL);
        } else if (Dv == 256) {
            copy_rows_kernel<256><<<blocks, threads>>>((float4*)out, BL);
        } else if (Dv == 128) {
            copy_rows_kernel<128><<<blocks, threads>>>((float4*)out, BL);
        } else if ((Dv & 31) == 0 && Dv == 64) {
            copy_rows_kernel<64><<<blocks, threads>>>((float4*)out, BL);
        } else {
            copy_rows_generic_kernel<<<blocks, threads>>>((float4*)out, BL, Dv);
        }
    } else {
        int threads = (int)(D < 1024 ? ((D + 31) / 32) * 32 : 1024);
        copy_scalar_kernel<<<BL, threads>>>(out, BL, (int)D);
    }
}